// round 7
// baseline (speedup 1.0000x reference)
#include <cuda_runtime.h>
#include <cuda_bf16.h>
#include <cstdint>

// Problem constants
#define B_ 32
#define T_ 32
#define S_ 100
#define H_ 512
#define E_ 300
#define V_ 45000
#define NOOV_ 10
#define VEXT_ 45010
#define NEG_INF_F (-1e12f)
#define NPAD_ 45056   // V_ padded to multiple of 128 for the MMA GEMM

// ---------------- scratch (device globals; no allocation allowed) ----------------
__device__ float g_cat[3200 * 1024];     // concat(tree_output, encoder_outputs)  13.1 MB
__device__ float g_mem[3200 * 512];      // memories [B,S,H]                       6.6 MB
__device__ float g_Wg[812 * 2048];       // stacked [W_ih; W_hh]                   6.7 MB
__device__ float g_bg[2048];             // b_ih + b_hh
__device__ float g_Aemb[1024 * 300];     // gathered embeddings per (t,b)
__device__ float g_Xemb[1024 * 300];     // X_emb = Aemb @ W_red[0:300] + b_red
__device__ float g_xh[2][32 * 812];      // per-step [x(300) | h(512)] double-buffered
__device__ float g_c[2][32 * 512];       // cell state double-buffered
__device__ float g_hc[32 * 1024];        // [h_new(512) | ctx_new(512)]
__device__ float g_gates[32 * 2048];     // LSTM pre-activations
__device__ float g_Z[1024 * 512];        // z for all steps (rows m = t*32+b)
__device__ float g_Energy[1024 * 100];   // masked energies per (t,b,s)
__device__ __nv_bfloat16 g_Wb[(size_t)NPAD_ * 512];  // W_out^T in bf16 [N,K]  46.1 MB
__device__ __nv_bfloat16 g_Zb[1024 * 512];           // Z in bf16              1 MB

__device__ __forceinline__ float sigf(float x) { return 1.0f / (1.0f + expf(-x)); }

// ---------------- prep kernels ----------------
__global__ void prep_cat_kernel(const float* __restrict__ tree,
                                const float* __restrict__ enc) {
    int idx = blockIdx.x * blockDim.x + threadIdx.x;
    if (idx >= 3200 * 1024) return;
    int m = idx >> 10, k = idx & 1023;
    g_cat[idx] = (k < 512) ? tree[m * 512 + k] : enc[m * 512 + (k - 512)];
}

__global__ void prep_wg_kernel(const float* __restrict__ W_ih, const float* __restrict__ W_hh,
                               const float* __restrict__ b_ih, const float* __restrict__ b_hh) {
    int idx = blockIdx.x * blockDim.x + threadIdx.x;
    if (idx < 2048) g_bg[idx] = b_ih[idx] + b_hh[idx];
    if (idx >= 812 * 2048) return;
    int r = idx >> 11, c = idx & 2047;
    g_Wg[idx] = (r < 300) ? W_ih[r * 2048 + c] : W_hh[(r - 300) * 2048 + c];
}

__global__ void prep_aemb_kernel(const int* __restrict__ trg,
                                 const float* __restrict__ embedding) {
    int idx = blockIdx.x * blockDim.x + threadIdx.x;
    if (idx >= 1024 * 300) return;
    int m = idx / 300, n = idx - m * 300;
    int t = m >> 5, b = m & 31;
    int tok = trg[b * T_ + t];          // trg_seq is [B,T] row-major; scan uses trg.T
    g_Aemb[idx] = embedding[(long)tok * E_ + n];
}

// transpose + bf16-convert W_out [512,45000] -> g_Wb [45056,512] (pad rows zeroed)
__global__ void convw_kernel(const float* __restrict__ W_out) {
    __shared__ float tile[32][33];
    int n0 = blockIdx.x * 32, k0 = blockIdx.y * 32;
    int tx = threadIdx.x, ty = threadIdx.y;  // 32 x 8
#pragma unroll
    for (int i = 0; i < 32; i += 8) {
        int k = k0 + ty + i, n = n0 + tx;
        tile[ty + i][tx] = (n < V_) ? W_out[(long)k * V_ + n] : 0.0f;
    }
    __syncthreads();
#pragma unroll
    for (int i = 0; i < 32; i += 8) {
        int n = n0 + ty + i, k = k0 + tx;
        g_Wb[(size_t)n * 512 + k] = __float2bfloat16(tile[tx][ty + i]);
    }
}

__global__ void convz_kernel() {
    int idx = blockIdx.x * blockDim.x + threadIdx.x;
    if (idx < 1024 * 512) g_Zb[idx] = __float2bfloat16(g_Z[idx]);
}

__global__ void init_state_kernel(const float* __restrict__ h0,
                                  const float* __restrict__ c0) {
    int idx = blockIdx.x * blockDim.x + threadIdx.x;
    if (idx < 32 * 812) {
        int b = idx / 812, k = idx - b * 812;
        g_xh[0][idx] = (k < 300) ? g_Xemb[b * 300 + k]
                                 : h0[b * 512 + (k - 300)];
    }
    if (idx < 32 * 512) g_c[0][idx] = c0[idx];
}

// ---------------- generic tiled fp32 GEMM (used for memories / X_emb) ----------------
__global__ void __launch_bounds__(256)
gemm64_kernel(const float* __restrict__ A, const float* __restrict__ B, int ldb,
              const float* __restrict__ bias, float* __restrict__ C, int ldc,
              int M, int N, int K) {
    __shared__ float As[16][68];
    __shared__ float Bs[16][68];
    int tid = threadIdx.x;
    int tx = tid & 15, ty = tid >> 4;
    int row0 = blockIdx.y * 64, col0 = blockIdx.x * 64;
    float acc[4][4];
#pragma unroll
    for (int i = 0; i < 4; i++)
#pragma unroll
        for (int j = 0; j < 4; j++) acc[i][j] = 0.0f;

    for (int k0 = 0; k0 < K; k0 += 16) {
#pragma unroll
        for (int i = 0; i < 4; i++) {
            int idx = tid + i * 256;
            int m = idx >> 4, kk = idx & 15;
            int gm = row0 + m, gk = k0 + kk;
            As[kk][m] = (gm < M && gk < K) ? A[(long)gm * K + gk] : 0.0f;
        }
#pragma unroll
        for (int i = 0; i < 4; i++) {
            int idx = tid + i * 256;
            int kk = idx >> 6, n = idx & 63;
            int gk = k0 + kk, gn = col0 + n;
            Bs[kk][n] = (gk < K && gn < N) ? B[(long)gk * ldb + gn] : 0.0f;
        }
        __syncthreads();
#pragma unroll
        for (int kk = 0; kk < 16; kk++) {
            float4 a4 = *(const float4*)&As[kk][ty * 4];
            float4 b4 = *(const float4*)&Bs[kk][tx * 4];
            float av[4] = {a4.x, a4.y, a4.z, a4.w};
            float bv[4] = {b4.x, b4.y, b4.z, b4.w};
#pragma unroll
            for (int i = 0; i < 4; i++)
#pragma unroll
                for (int j = 0; j < 4; j++) acc[i][j] += av[i] * bv[j];
        }
        __syncthreads();
    }
#pragma unroll
    for (int i = 0; i < 4; i++) {
        int m = row0 + ty * 4 + i;
        if (m >= M) continue;
#pragma unroll
        for (int j = 0; j < 4; j++) {
            int n = col0 + tx * 4 + j;
            if (n >= N) continue;
            C[(long)m * ldc + n] = acc[i][j] + (bias ? bias[n] : 0.0f);
        }
    }
}

// ---------------- bf16 tensor-core logits GEMM ----------------
// out[b*32+t, n] = Zb[t*32+b, :] . Wb[n, :] + b_out[n]
// BM=128, BN=128, BK=32. 8 warps (2x4), warp tile 64x32, mma m16n8k16.
#define ASTR 40   // smem row stride in bf16 (20 words -> conflict-free frag loads)
__global__ void __launch_bounds__(256)
mma_logits_kernel(const __nv_bfloat16* __restrict__ A,   // [1024,512]
                  const __nv_bfloat16* __restrict__ Bm,  // [NPAD_,512]
                  const float* __restrict__ bias,
                  float* __restrict__ out) {
    __shared__ __nv_bfloat16 As[128 * ASTR];
    __shared__ __nv_bfloat16 Bs[128 * ASTR];
    int tid = threadIdx.x;
    int wid = tid >> 5, lane = tid & 31;
    int wm = wid >> 2, wn = wid & 3;
    int tq = lane >> 2, tr = lane & 3;
    int row0 = blockIdx.y * 128;
    int col0 = blockIdx.x * 128;

    float acc[4][4][4];
#pragma unroll
    for (int a = 0; a < 4; a++)
#pragma unroll
        for (int b = 0; b < 4; b++)
#pragma unroll
            for (int c = 0; c < 4; c++) acc[a][b][c] = 0.0f;

    int ldr_r = tid >> 2;           // 0..63  (+64 on 2nd pass)
    int ldr_c = (tid & 3) * 8;      // 0,8,16,24

    for (int k0 = 0; k0 < 512; k0 += 32) {
#pragma unroll
        for (int pass = 0; pass < 2; pass++) {
            int r = ldr_r + pass * 64;
            uint4 va = *(const uint4*)(A + (size_t)(row0 + r) * 512 + k0 + ldr_c);
            *(uint4*)&As[r * ASTR + ldr_c] = va;
            uint4 vb = *(const uint4*)(Bm + (size_t)(col0 + r) * 512 + k0 + ldr_c);
            *(uint4*)&Bs[r * ASTR + ldr_c] = vb;
        }
        __syncthreads();
#pragma unroll
        for (int ks = 0; ks < 2; ks++) {
            int kb = ks * 16 + tr * 2;
            uint32_t afr[4][4], bfr[4][2];
#pragma unroll
            for (int mt = 0; mt < 4; mt++) {
                int r = wm * 64 + mt * 16 + tq;
                afr[mt][0] = *(const uint32_t*)&As[r * ASTR + kb];
                afr[mt][1] = *(const uint32_t*)&As[(r + 8) * ASTR + kb];
                afr[mt][2] = *(const uint32_t*)&As[r * ASTR + kb + 8];
                afr[mt][3] = *(const uint32_t*)&As[(r + 8) * ASTR + kb + 8];
            }
#pragma unroll
            for (int nt = 0; nt < 4; nt++) {
                int r = wn * 32 + nt * 8 + tq;
                bfr[nt][0] = *(const uint32_t*)&Bs[r * ASTR + kb];
                bfr[nt][1] = *(const uint32_t*)&Bs[r * ASTR + kb + 8];
            }
#pragma unroll
            for (int mt = 0; mt < 4; mt++)
#pragma unroll
                for (int nt = 0; nt < 4; nt++) {
                    asm volatile(
                        "mma.sync.aligned.m16n8k16.row.col.f32.bf16.bf16.f32 "
                        "{%0,%1,%2,%3}, {%4,%5,%6,%7}, {%8,%9}, {%0,%1,%2,%3};"
                        : "+f"(acc[mt][nt][0]), "+f"(acc[mt][nt][1]),
                          "+f"(acc[mt][nt][2]), "+f"(acc[mt][nt][3])
                        : "r"(afr[mt][0]), "r"(afr[mt][1]),
                          "r"(afr[mt][2]), "r"(afr[mt][3]),
                          "r"(bfr[nt][0]), "r"(bfr[nt][1]));
                }
        }
        __syncthreads();
    }

    // store with row remap (t*32+b -> b*32+t) and N bound
#pragma unroll
    for (int mt = 0; mt < 4; mt++) {
#pragma unroll
        for (int half = 0; half < 2; half++) {
            int m = row0 + wm * 64 + mt * 16 + tq + half * 8;
            int orow = ((m & 31) << 5) + (m >> 5);
            float* orow_p = out + (size_t)orow * VEXT_;
#pragma unroll
            for (int nt = 0; nt < 4; nt++) {
                int n = col0 + wn * 32 + nt * 8 + tr * 2;
                if (n < V_)     orow_p[n]     = acc[mt][nt][half * 2 + 0] + bias[n];
                if (n + 1 < V_) orow_p[n + 1] = acc[mt][nt][half * 2 + 1] + bias[n + 1];
            }
        }
    }
}

// ---------------- small GEMM: 32 rows, per-block 16 cols ----------------
__global__ void __launch_bounds__(256)
small_gemm_kernel(const float* __restrict__ A, int lda, int K,
                  const float* __restrict__ B, int ldb,
                  const float* __restrict__ bias,
                  const float* __restrict__ addm, int ldadd,
                  float* __restrict__ C, int ldc, int N, int act) {
    __shared__ float As[32][33];
    int tid = threadIdx.x;
    int tx = tid & 15, ty = tid >> 4;
    int n = blockIdx.x * 16 + tx;
    float acc0 = 0.0f, acc1 = 0.0f;
    for (int k0 = 0; k0 < K; k0 += 32) {
#pragma unroll
        for (int i = 0; i < 4; i++) {
            int idx = tid + i * 256;
            int m = idx >> 5, kk = idx & 31;
            As[m][kk] = (k0 + kk < K) ? A[m * lda + k0 + kk] : 0.0f;
        }
        __syncthreads();
        if (n < N) {
#pragma unroll 8
            for (int kk = 0; kk < 32; kk++) {
                int gk = k0 + kk;
                float bv = (gk < K) ? B[(long)gk * ldb + n] : 0.0f;
                acc0 += As[ty][kk] * bv;
                acc1 += As[ty + 16][kk] * bv;
            }
        }
        __syncthreads();
    }
    if (n < N) {
        float base = bias ? bias[n] : 0.0f;
        float r0 = acc0 + base + (addm ? addm[ty * ldadd + n] : 0.0f);
        float r1 = acc1 + base + (addm ? addm[(ty + 16) * ldadd + n] : 0.0f);
        if (act) { r0 = tanhf(r0); r1 = tanhf(r1); }
        C[ty * ldc + n] = r0;
        C[(ty + 16) * ldc + n] = r1;
    }
}

// ---------------- fused LSTM nonlinearity + attention ----------------
__global__ void __launch_bounds__(256)
lstm_attn_kernel(int t, int p, const unsigned char* __restrict__ mask) {
    int b = blockIdx.x, tid = threadIdx.x;
    __shared__ float h_s[512];
    __shared__ float e_s[100];
    __shared__ float a_s[100];
    __shared__ float sred;

    const float* g = g_gates + b * 2048;
    const float* cp = g_c[p] + b * 512;
    float* cn = g_c[1 - p] + b * 512;
    for (int j = tid; j < 512; j += 256) {
        float gi = g[j], gf = g[512 + j], gg = g[1024 + j], go = g[1536 + j];
        float c = sigf(gf) * cp[j] + sigf(gi) * tanhf(gg);
        float h = sigf(go) * tanhf(c);
        cn[j] = c;
        h_s[j] = h;
        g_xh[1 - p][b * 812 + 300 + j] = h;
        g_hc[b * 1024 + j] = h;
    }
    __syncthreads();

    int w = tid >> 5, lane = tid & 31;
    for (int s = w; s < 100; s += 8) {
        const float* mrow = g_mem + ((long)(b * S_ + s)) * 512;
        float acc = 0.0f;
#pragma unroll 4
        for (int j = lane; j < 512; j += 32) acc += h_s[j] * mrow[j];
#pragma unroll
        for (int o = 16; o; o >>= 1) acc += __shfl_xor_sync(0xffffffffu, acc, o);
        if (lane == 0) {
            float e = mask[b * S_ + s] ? NEG_INF_F : acc;
            e_s[s] = e;
            g_Energy[(t * 32 + b) * 100 + s] = e;
        }
    }
    __syncthreads();

    if (tid < 32) {
        float m = -3e38f;
        for (int s = lane; s < 100; s += 32) m = fmaxf(m, e_s[s]);
#pragma unroll
        for (int o = 16; o; o >>= 1) m = fmaxf(m, __shfl_xor_sync(0xffffffffu, m, o));
        float sum = 0.0f;
        for (int s = lane; s < 100; s += 32) {
            float v = expf(e_s[s] - m);
            a_s[s] = v;
            sum += v;
        }
#pragma unroll
        for (int o = 16; o; o >>= 1) sum += __shfl_xor_sync(0xffffffffu, sum, o);
        if (lane == 0) sred = sum;
    }
    __syncthreads();

    float inv = 1.0f / sred;
    for (int j = tid; j < 512; j += 256) {
        float acc = 0.0f;
#pragma unroll 5
        for (int s = 0; s < 100; s++) acc += a_s[s] * g_mem[((long)(b * S_ + s)) * 512 + j];
        g_hc[b * 1024 + 512 + j] = acc * inv;
    }
}

// ---------------- output assembly ----------------
__global__ void oov_fill_kernel(float* __restrict__ out) {
    int idx = blockIdx.x * blockDim.x + threadIdx.x;
    if (idx >= 1024 * NOOV_) return;
    int row = idx / NOOV_, v = V_ + (idx - row * NOOV_);
    out[(long)row * VEXT_ + v] = NEG_INF_F;
}

__global__ void scatter_kernel(const int* __restrict__ ext_src, float* __restrict__ out) {
    int bt = blockIdx.x;            // row index = b*32 + t
    int b = bt >> 5, t = bt & 31;
    __shared__ int pos_s[100];
    __shared__ float en_s[100];
    int tid = threadIdx.x;
    if (tid < 100) {
        pos_s[tid] = ext_src[b * S_ + tid];
        en_s[tid] = g_Energy[(t * 32 + b) * 100 + tid];
    }
    __syncthreads();
    if (tid < 100) {
        int pos = pos_s[tid];
        bool owner = true;
        float m = en_s[tid];
        for (int s = 0; s < 100; s++) {
            if (s == tid) continue;
            if (pos_s[s] == pos) {
                if (s < tid) owner = false;
                m = fmaxf(m, en_s[s]);
            }
        }
        if (owner && m != NEG_INF_F) {
            long off = (long)bt * VEXT_ + pos;
            float base = (pos < V_) ? out[off] : 0.0f;
            float val = base + m;
            if (val == 0.0f) val = NEG_INF_F;
            out[off] = val;
        }
    }
}

// ---------------- launch ----------------
extern "C" void kernel_launch(void* const* d_in, const int* in_sizes, int n_in,
                              void* d_out, int out_size) {
    const int* trg       = (const int*)d_in[0];
    const int* ext_src   = (const int*)d_in[1];
    const float* h0      = (const float*)d_in[2];
    const float* c0      = (const float*)d_in[3];
    const float* tree    = (const float*)d_in[4];
    const float* enc     = (const float*)d_in[6];
    const unsigned char* mask = (const unsigned char*)d_in[7];
    const float* embedding = (const float*)d_in[8];
    const float* W_enc   = (const float*)d_in[9];
    const float* b_enc   = (const float*)d_in[10];
    const float* W_red   = (const float*)d_in[11];
    const float* b_red   = (const float*)d_in[12];
    const float* W_ih    = (const float*)d_in[13];
    const float* W_hh    = (const float*)d_in[14];
    const float* b_ih    = (const float*)d_in[15];
    const float* b_hh    = (const float*)d_in[16];
    const float* W_cat   = (const float*)d_in[17];
    const float* b_cat   = (const float*)d_in[18];
    const float* W_out   = (const float*)d_in[19];
    const float* b_out   = (const float*)d_in[20];
    float* out = (float*)d_out;

    float *cat_p, *mem_p, *Wg_p, *bg_p, *Aemb_p, *Xemb_p, *xh_p, *hc_p, *gates_p, *Z_p;
    __nv_bfloat16 *Wb_p, *Zb_p;
    cudaGetSymbolAddress((void**)&cat_p,   g_cat);
    cudaGetSymbolAddress((void**)&mem_p,   g_mem);
    cudaGetSymbolAddress((void**)&Wg_p,    g_Wg);
    cudaGetSymbolAddress((void**)&bg_p,    g_bg);
    cudaGetSymbolAddress((void**)&Aemb_p,  g_Aemb);
    cudaGetSymbolAddress((void**)&Xemb_p,  g_Xemb);
    cudaGetSymbolAddress((void**)&xh_p,    g_xh);
    cudaGetSymbolAddress((void**)&hc_p,    g_hc);
    cudaGetSymbolAddress((void**)&gates_p, g_gates);
    cudaGetSymbolAddress((void**)&Z_p,     g_Z);
    cudaGetSymbolAddress((void**)&Wb_p,    g_Wb);
    cudaGetSymbolAddress((void**)&Zb_p,    g_Zb);

    // --- prep (all independent) ---
    prep_cat_kernel<<<(3200 * 1024 + 255) / 256, 256>>>(tree, enc);
    prep_wg_kernel<<<(812 * 2048 + 255) / 256, 256>>>(W_ih, W_hh, b_ih, b_hh);
    prep_aemb_kernel<<<(1024 * 300 + 255) / 256, 256>>>(trg, embedding);
    convw_kernel<<<dim3(NPAD_ / 32, 512 / 32), dim3(32, 8)>>>(W_out);

    // memories = cat @ W_enc + b_enc      [3200,512], K=1024
    gemm64_kernel<<<dim3(8, 50), 256>>>(cat_p, W_enc, 512, b_enc, mem_p, 512,
                                        3200, 512, 1024);
    // X_emb = Aemb @ W_red[0:300,:] + b_red   [1024,300], K=300
    gemm64_kernel<<<dim3(5, 16), 256>>>(Aemb_p, W_red, 300, b_red, Xemb_p, 300,
                                        1024, 300, 300);
    init_state_kernel<<<(32 * 812 + 255) / 256, 256>>>(h0, c0);

    // --- recurrence: 32 steps ---
    for (int t = 0; t < T_; t++) {
        int p = t & 1;
        small_gemm_kernel<<<128, 256>>>(xh_p + p * 32 * 812, 812, 812,
                                        Wg_p, 2048, bg_p, nullptr, 0,
                                        gates_p, 2048, 2048, 0);
        lstm_attn_kernel<<<32, 256>>>(t, p, mask);
        small_gemm_kernel<<<32, 256>>>(hc_p, 1024, 1024,
                                       W_cat, 512, b_cat, nullptr, 0,
                                       Z_p + (long)t * 32 * 512, 512, 512, 1);
        if (t + 1 < T_) {
            small_gemm_kernel<<<19, 256>>>(hc_p + 512, 1024, 512,
                                           W_red + 300 * 300, 300, nullptr,
                                           Xemb_p + (long)(t + 1) * 32 * 300, 300,
                                           xh_p + (1 - p) * 32 * 812, 812, 300, 0);
        }
    }

    // --- hoisted logits GEMM on tensor cores (bf16 in, fp32 accum) ---
    convz_kernel<<<(1024 * 512 + 255) / 256, 256>>>();
    mma_logits_kernel<<<dim3(NPAD_ / 128, 1024 / 128), 256>>>(Zb_p, Wb_p, b_out, out);

    // --- OOV default (-INF), then pointer scatter-max ---
    oov_fill_kernel<<<(1024 * NOOV_ + 255) / 256, 256>>>(out);
    scatter_kernel<<<1024, 128>>>(ext_src, out);
}

// round 8
// speedup vs baseline: 1.4432x; 1.4432x over previous
#include <cuda_runtime.h>
#include <cuda_bf16.h>
#include <cstdint>

// Problem constants
#define B_ 32
#define T_ 32
#define S_ 100
#define H_ 512
#define E_ 300
#define V_ 45000
#define NOOV_ 10
#define VEXT_ 45010
#define NEG_INF_F (-1e12f)
#define NPAD_ 45056   // V_ padded to multiple of 128 for the MMA GEMM

// ---------------- scratch (device globals; no allocation allowed) ----------------
__device__ float g_cat[3200 * 1024];     // concat(tree_output, encoder_outputs)  13.1 MB
__device__ float g_mem[3200 * 512];      // memories [B,S,H]                       6.6 MB
__device__ float g_Wg[812 * 2048];       // stacked [W_ih; W_hh]                   6.7 MB
__device__ float g_bg[2048];             // b_ih + b_hh
__device__ float g_Aemb[1024 * 300];     // gathered embeddings per (t,b)
__device__ float g_Xemb[1024 * 300];     // X_emb = Aemb @ W_red[0:300] + b_red
__device__ float g_xh[2][32 * 812];      // per-step [x(300) | h(512)] double-buffered
__device__ float g_c[2][32 * 512];       // cell state double-buffered
__device__ float g_hc[32 * 1024];        // [h_new(512) | ctx_new(512)]
__device__ float g_gates[32 * 2048];     // LSTM pre-activations
__device__ float g_Z[1024 * 512];        // z for all steps (rows m = t*32+b)
__device__ float g_Energy[1024 * 100];   // masked energies per (t,b,s)
__device__ __nv_bfloat16 g_Wb[(size_t)NPAD_ * 512];  // W_out^T in bf16 [N,K]  46.1 MB
__device__ __nv_bfloat16 g_Zb[1024 * 512];           // Z in bf16              1 MB

__device__ __forceinline__ float sigf(float x) { return 1.0f / (1.0f + expf(-x)); }

// ---------------- prep kernels ----------------
__global__ void prep_cat_kernel(const float* __restrict__ tree,
                                const float* __restrict__ enc) {
    int idx = blockIdx.x * blockDim.x + threadIdx.x;
    if (idx >= 3200 * 1024) return;
    int m = idx >> 10, k = idx & 1023;
    g_cat[idx] = (k < 512) ? tree[m * 512 + k] : enc[m * 512 + (k - 512)];
}

__global__ void prep_wg_kernel(const float* __restrict__ W_ih, const float* __restrict__ W_hh,
                               const float* __restrict__ b_ih, const float* __restrict__ b_hh) {
    int idx = blockIdx.x * blockDim.x + threadIdx.x;
    if (idx < 2048) g_bg[idx] = b_ih[idx] + b_hh[idx];
    if (idx >= 812 * 2048) return;
    int r = idx >> 11, c = idx & 2047;
    g_Wg[idx] = (r < 300) ? W_ih[r * 2048 + c] : W_hh[(r - 300) * 2048 + c];
}

__global__ void prep_aemb_kernel(const int* __restrict__ trg,
                                 const float* __restrict__ embedding) {
    int idx = blockIdx.x * blockDim.x + threadIdx.x;
    if (idx >= 1024 * 300) return;
    int m = idx / 300, n = idx - m * 300;
    int t = m >> 5, b = m & 31;
    int tok = trg[b * T_ + t];          // trg_seq is [B,T] row-major; scan uses trg.T
    g_Aemb[idx] = embedding[(long)tok * E_ + n];
}

// transpose + bf16-convert W_out [512,45000] -> g_Wb [45056,512] (pad rows zeroed)
__global__ void convw_kernel(const float* __restrict__ W_out) {
    __shared__ float tile[32][33];
    int n0 = blockIdx.x * 32, k0 = blockIdx.y * 32;
    int tx = threadIdx.x, ty = threadIdx.y;  // 32 x 8
#pragma unroll
    for (int i = 0; i < 32; i += 8) {
        int k = k0 + ty + i, n = n0 + tx;
        tile[ty + i][tx] = (n < V_) ? W_out[(long)k * V_ + n] : 0.0f;
    }
    __syncthreads();
#pragma unroll
    for (int i = 0; i < 32; i += 8) {
        int n = n0 + ty + i, k = k0 + tx;
        g_Wb[(size_t)n * 512 + k] = __float2bfloat16(tile[tx][ty + i]);
    }
}

__global__ void convz_kernel() {
    int idx = blockIdx.x * blockDim.x + threadIdx.x;
    if (idx < 1024 * 512) g_Zb[idx] = __float2bfloat16(g_Z[idx]);
}

__global__ void init_state_kernel(const float* __restrict__ h0,
                                  const float* __restrict__ c0) {
    int idx = blockIdx.x * blockDim.x + threadIdx.x;
    if (idx < 32 * 812) {
        int b = idx / 812, k = idx - b * 812;
        g_xh[0][idx] = (k < 300) ? g_Xemb[b * 300 + k]
                                 : h0[b * 512 + (k - 300)];
    }
    if (idx < 32 * 512) g_c[0][idx] = c0[idx];
}

// ---------------- generic tiled fp32 GEMM (used for memories / X_emb) ----------------
__global__ void __launch_bounds__(256)
gemm64_kernel(const float* __restrict__ A, const float* __restrict__ B, int ldb,
              const float* __restrict__ bias, float* __restrict__ C, int ldc,
              int M, int N, int K) {
    __shared__ float As[16][68];
    __shared__ float Bs[16][68];
    int tid = threadIdx.x;
    int tx = tid & 15, ty = tid >> 4;
    int row0 = blockIdx.y * 64, col0 = blockIdx.x * 64;
    float acc[4][4];
#pragma unroll
    for (int i = 0; i < 4; i++)
#pragma unroll
        for (int j = 0; j < 4; j++) acc[i][j] = 0.0f;

    for (int k0 = 0; k0 < K; k0 += 16) {
#pragma unroll
        for (int i = 0; i < 4; i++) {
            int idx = tid + i * 256;
            int m = idx >> 4, kk = idx & 15;
            int gm = row0 + m, gk = k0 + kk;
            As[kk][m] = (gm < M && gk < K) ? A[(long)gm * K + gk] : 0.0f;
        }
#pragma unroll
        for (int i = 0; i < 4; i++) {
            int idx = tid + i * 256;
            int kk = idx >> 6, n = idx & 63;
            int gk = k0 + kk, gn = col0 + n;
            Bs[kk][n] = (gk < K && gn < N) ? B[(long)gk * ldb + gn] : 0.0f;
        }
        __syncthreads();
#pragma unroll
        for (int kk = 0; kk < 16; kk++) {
            float4 a4 = *(const float4*)&As[kk][ty * 4];
            float4 b4 = *(const float4*)&Bs[kk][tx * 4];
            float av[4] = {a4.x, a4.y, a4.z, a4.w};
            float bv[4] = {b4.x, b4.y, b4.z, b4.w};
#pragma unroll
            for (int i = 0; i < 4; i++)
#pragma unroll
                for (int j = 0; j < 4; j++) acc[i][j] += av[i] * bv[j];
        }
        __syncthreads();
    }
#pragma unroll
    for (int i = 0; i < 4; i++) {
        int m = row0 + ty * 4 + i;
        if (m >= M) continue;
#pragma unroll
        for (int j = 0; j < 4; j++) {
            int n = col0 + tx * 4 + j;
            if (n >= N) continue;
            C[(long)m * ldc + n] = acc[i][j] + (bias ? bias[n] : 0.0f);
        }
    }
}

// ---------------- bf16 tensor-core logits GEMM ----------------
// out[b*32+t, n] = Zb[t*32+b, :] . Wb[n, :] + b_out[n]
// BM=128, BN=128, BK=32. 8 warps (2x4), warp tile 64x32, mma m16n8k16.
#define ASTR 40   // smem row stride in bf16 (20 words -> conflict-free frag loads)
__global__ void __launch_bounds__(256)
mma_logits_kernel(const __nv_bfloat16* __restrict__ A,   // [1024,512]
                  const __nv_bfloat16* __restrict__ Bm,  // [NPAD_,512]
                  const float* __restrict__ bias,
                  float* __restrict__ out) {
    __shared__ __nv_bfloat16 As[128 * ASTR];
    __shared__ __nv_bfloat16 Bs[128 * ASTR];
    int tid = threadIdx.x;
    int wid = tid >> 5, lane = tid & 31;
    int wm = wid >> 2, wn = wid & 3;
    int tq = lane >> 2, tr = lane & 3;
    int row0 = blockIdx.y * 128;
    int col0 = blockIdx.x * 128;

    float acc[4][4][4];
#pragma unroll
    for (int a = 0; a < 4; a++)
#pragma unroll
        for (int b = 0; b < 4; b++)
#pragma unroll
            for (int c = 0; c < 4; c++) acc[a][b][c] = 0.0f;

    int ldr_r = tid >> 2;           // 0..63  (+64 on 2nd pass)
    int ldr_c = (tid & 3) * 8;      // 0,8,16,24

    for (int k0 = 0; k0 < 512; k0 += 32) {
#pragma unroll
        for (int pass = 0; pass < 2; pass++) {
            int r = ldr_r + pass * 64;
            uint4 va = *(const uint4*)(A + (size_t)(row0 + r) * 512 + k0 + ldr_c);
            *(uint4*)&As[r * ASTR + ldr_c] = va;
            uint4 vb = *(const uint4*)(Bm + (size_t)(col0 + r) * 512 + k0 + ldr_c);
            *(uint4*)&Bs[r * ASTR + ldr_c] = vb;
        }
        __syncthreads();
#pragma unroll
        for (int ks = 0; ks < 2; ks++) {
            int kb = ks * 16 + tr * 2;
            uint32_t afr[4][4], bfr[4][2];
#pragma unroll
            for (int mt = 0; mt < 4; mt++) {
                int r = wm * 64 + mt * 16 + tq;
                afr[mt][0] = *(const uint32_t*)&As[r * ASTR + kb];
                afr[mt][1] = *(const uint32_t*)&As[(r + 8) * ASTR + kb];
                afr[mt][2] = *(const uint32_t*)&As[r * ASTR + kb + 8];
                afr[mt][3] = *(const uint32_t*)&As[(r + 8) * ASTR + kb + 8];
            }
#pragma unroll
            for (int nt = 0; nt < 4; nt++) {
                int r = wn * 32 + nt * 8 + tq;
                bfr[nt][0] = *(const uint32_t*)&Bs[r * ASTR + kb];
                bfr[nt][1] = *(const uint32_t*)&Bs[r * ASTR + kb + 8];
            }
#pragma unroll
            for (int mt = 0; mt < 4; mt++)
#pragma unroll
                for (int nt = 0; nt < 4; nt++) {
                    asm volatile(
                        "mma.sync.aligned.m16n8k16.row.col.f32.bf16.bf16.f32 "
                        "{%0,%1,%2,%3}, {%4,%5,%6,%7}, {%8,%9}, {%0,%1,%2,%3};"
                        : "+f"(acc[mt][nt][0]), "+f"(acc[mt][nt][1]),
                          "+f"(acc[mt][nt][2]), "+f"(acc[mt][nt][3])
                        : "r"(afr[mt][0]), "r"(afr[mt][1]),
                          "r"(afr[mt][2]), "r"(afr[mt][3]),
                          "r"(bfr[nt][0]), "r"(bfr[nt][1]));
                }
        }
        __syncthreads();
    }

    // store with row remap (t*32+b -> b*32+t) and N bound
#pragma unroll
    for (int mt = 0; mt < 4; mt++) {
#pragma unroll
        for (int half = 0; half < 2; half++) {
            int m = row0 + wm * 64 + mt * 16 + tq + half * 8;
            int orow = ((m & 31) << 5) + (m >> 5);
            float* orow_p = out + (size_t)orow * VEXT_;
#pragma unroll
            for (int nt = 0; nt < 4; nt++) {
                int n = col0 + wn * 32 + nt * 8 + tr * 2;
                if (n < V_)     orow_p[n]     = acc[mt][nt][half * 2 + 0] + bias[n];
                if (n + 1 < V_) orow_p[n + 1] = acc[mt][nt][half * 2 + 1] + bias[n + 1];
            }
        }
    }
}

// ---------------- small GEMM: 32 rows, per-block 16 cols ----------------
__global__ void __launch_bounds__(256)
small_gemm_kernel(const float* __restrict__ A, int lda, int K,
                  const float* __restrict__ B, int ldb,
                  const float* __restrict__ bias,
                  const float* __restrict__ addm, int ldadd,
                  float* __restrict__ C, int ldc, int N, int act) {
    __shared__ float As[32][33];
    int tid = threadIdx.x;
    int tx = tid & 15, ty = tid >> 4;
    int n = blockIdx.x * 16 + tx;
    float acc0 = 0.0f, acc1 = 0.0f;
    for (int k0 = 0; k0 < K; k0 += 32) {
#pragma unroll
        for (int i = 0; i < 4; i++) {
            int idx = tid + i * 256;
            int m = idx >> 5, kk = idx & 31;
            As[m][kk] = (k0 + kk < K) ? A[m * lda + k0 + kk] : 0.0f;
        }
        __syncthreads();
        if (n < N) {
#pragma unroll 8
            for (int kk = 0; kk < 32; kk++) {
                int gk = k0 + kk;
                float bv = (gk < K) ? B[(long)gk * ldb + n] : 0.0f;
                acc0 += As[ty][kk] * bv;
                acc1 += As[ty + 16][kk] * bv;
            }
        }
        __syncthreads();
    }
    if (n < N) {
        float base = bias ? bias[n] : 0.0f;
        float r0 = acc0 + base + (addm ? addm[ty * ldadd + n] : 0.0f);
        float r1 = acc1 + base + (addm ? addm[(ty + 16) * ldadd + n] : 0.0f);
        if (act) { r0 = tanhf(r0); r1 = tanhf(r1); }
        C[ty * ldc + n] = r0;
        C[(ty + 16) * ldc + n] = r1;
    }
}

// ---------------- fused LSTM nonlinearity + attention ----------------
__global__ void __launch_bounds__(256)
lstm_attn_kernel(int t, int p, const unsigned char* __restrict__ mask) {
    int b = blockIdx.x, tid = threadIdx.x;
    __shared__ float h_s[512];
    __shared__ float e_s[100];
    __shared__ float a_s[100];
    __shared__ float sred;

    const float* g = g_gates + b * 2048;
    const float* cp = g_c[p] + b * 512;
    float* cn = g_c[1 - p] + b * 512;
    for (int j = tid; j < 512; j += 256) {
        float gi = g[j], gf = g[512 + j], gg = g[1024 + j], go = g[1536 + j];
        float c = sigf(gf) * cp[j] + sigf(gi) * tanhf(gg);
        float h = sigf(go) * tanhf(c);
        cn[j] = c;
        h_s[j] = h;
        g_xh[1 - p][b * 812 + 300 + j] = h;
        g_hc[b * 1024 + j] = h;
    }
    __syncthreads();

    int w = tid >> 5, lane = tid & 31;
    for (int s = w; s < 100; s += 8) {
        const float* mrow = g_mem + ((long)(b * S_ + s)) * 512;
        float acc = 0.0f;
#pragma unroll 4
        for (int j = lane; j < 512; j += 32) acc += h_s[j] * mrow[j];
#pragma unroll
        for (int o = 16; o; o >>= 1) acc += __shfl_xor_sync(0xffffffffu, acc, o);
        if (lane == 0) {
            float e = mask[b * S_ + s] ? NEG_INF_F : acc;
            e_s[s] = e;
            g_Energy[(t * 32 + b) * 100 + s] = e;
        }
    }
    __syncthreads();

    if (tid < 32) {
        float m = -3e38f;
        for (int s = lane; s < 100; s += 32) m = fmaxf(m, e_s[s]);
#pragma unroll
        for (int o = 16; o; o >>= 1) m = fmaxf(m, __shfl_xor_sync(0xffffffffu, m, o));
        float sum = 0.0f;
        for (int s = lane; s < 100; s += 32) {
            float v = expf(e_s[s] - m);
            a_s[s] = v;
            sum += v;
        }
#pragma unroll
        for (int o = 16; o; o >>= 1) sum += __shfl_xor_sync(0xffffffffu, sum, o);
        if (lane == 0) sred = sum;
    }
    __syncthreads();

    float inv = 1.0f / sred;
    for (int j = tid; j < 512; j += 256) {
        float acc = 0.0f;
#pragma unroll 5
        for (int s = 0; s < 100; s++) acc += a_s[s] * g_mem[((long)(b * S_ + s)) * 512 + j];
        g_hc[b * 1024 + 512 + j] = acc * inv;
    }
}

// ---------------- output assembly ----------------
__global__ void oov_fill_kernel(float* __restrict__ out) {
    int idx = blockIdx.x * blockDim.x + threadIdx.x;
    if (idx >= 1024 * NOOV_) return;
    int row = idx / NOOV_, v = V_ + (idx - row * NOOV_);
    out[(long)row * VEXT_ + v] = NEG_INF_F;
}

__global__ void scatter_kernel(const int* __restrict__ ext_src, float* __restrict__ out) {
    int bt = blockIdx.x;            // row index = b*32 + t
    int b = bt >> 5, t = bt & 31;
    __shared__ int pos_s[100];
    __shared__ float en_s[100];
    int tid = threadIdx.x;
    if (tid < 100) {
        pos_s[tid] = ext_src[b * S_ + tid];
        en_s[tid] = g_Energy[(t * 32 + b) * 100 + tid];
    }
    __syncthreads();
    if (tid < 100) {
        int pos = pos_s[tid];
        bool owner = true;
        float m = en_s[tid];
        for (int s = 0; s < 100; s++) {
            if (s == tid) continue;
            if (pos_s[s] == pos) {
                if (s < tid) owner = false;
                m = fmaxf(m, en_s[s]);
            }
        }
        if (owner && m != NEG_INF_F) {
            long off = (long)bt * VEXT_ + pos;
            float base = (pos < V_) ? out[off] : 0.0f;
            float val = base + m;
            if (val == 0.0f) val = NEG_INF_F;
            out[off] = val;
        }
    }
}

// ---------------- launch ----------------
extern "C" void kernel_launch(void* const* d_in, const int* in_sizes, int n_in,
                              void* d_out, int out_size) {
    const int* trg       = (const int*)d_in[0];
    const int* ext_src   = (const int*)d_in[1];
    const float* h0      = (const float*)d_in[2];
    const float* c0      = (const float*)d_in[3];
    const float* tree    = (const float*)d_in[4];
    const float* enc     = (const float*)d_in[6];
    const unsigned char* mask = (const unsigned char*)d_in[7];
    const float* embedding = (const float*)d_in[8];
    const float* W_enc   = (const float*)d_in[9];
    const float* b_enc   = (const float*)d_in[10];
    const float* W_red   = (const float*)d_in[11];
    const float* b_red   = (const float*)d_in[12];
    const float* W_ih    = (const float*)d_in[13];
    const float* W_hh    = (const float*)d_in[14];
    const float* b_ih    = (const float*)d_in[15];
    const float* b_hh    = (const float*)d_in[16];
    const float* W_cat   = (const float*)d_in[17];
    const float* b_cat   = (const float*)d_in[18];
    const float* W_out   = (const float*)d_in[19];
    const float* b_out   = (const float*)d_in[20];
    float* out = (float*)d_out;

    float *cat_p, *mem_p, *Wg_p, *bg_p, *Aemb_p, *Xemb_p, *xh_p, *hc_p, *gates_p, *Z_p;
    __nv_bfloat16 *Wb_p, *Zb_p;
    cudaGetSymbolAddress((void**)&cat_p,   g_cat);
    cudaGetSymbolAddress((void**)&mem_p,   g_mem);
    cudaGetSymbolAddress((void**)&Wg_p,    g_Wg);
    cudaGetSymbolAddress((void**)&bg_p,    g_bg);
    cudaGetSymbolAddress((void**)&Aemb_p,  g_Aemb);
    cudaGetSymbolAddress((void**)&Xemb_p,  g_Xemb);
    cudaGetSymbolAddress((void**)&xh_p,    g_xh);
    cudaGetSymbolAddress((void**)&hc_p,    g_hc);
    cudaGetSymbolAddress((void**)&gates_p, g_gates);
    cudaGetSymbolAddress((void**)&Z_p,     g_Z);
    cudaGetSymbolAddress((void**)&Wb_p,    g_Wb);
    cudaGetSymbolAddress((void**)&Zb_p,    g_Zb);

    // --- prep (all independent) ---
    prep_cat_kernel<<<(3200 * 1024 + 255) / 256, 256>>>(tree, enc);
    prep_wg_kernel<<<(812 * 2048 + 255) / 256, 256>>>(W_ih, W_hh, b_ih, b_hh);
    prep_aemb_kernel<<<(1024 * 300 + 255) / 256, 256>>>(trg, embedding);
    convw_kernel<<<dim3(NPAD_ / 32, 512 / 32), dim3(32, 8)>>>(W_out);

    // memories = cat @ W_enc + b_enc      [3200,512], K=1024
    gemm64_kernel<<<dim3(8, 50), 256>>>(cat_p, W_enc, 512, b_enc, mem_p, 512,
                                        3200, 512, 1024);
    // X_emb = Aemb @ W_red[0:300,:] + b_red   [1024,300], K=300
    gemm64_kernel<<<dim3(5, 16), 256>>>(Aemb_p, W_red, 300, b_red, Xemb_p, 300,
                                        1024, 300, 300);
    init_state_kernel<<<(32 * 812 + 255) / 256, 256>>>(h0, c0);

    // --- recurrence: 32 steps ---
    for (int t = 0; t < T_; t++) {
        int p = t & 1;
        small_gemm_kernel<<<128, 256>>>(xh_p + p * 32 * 812, 812, 812,
                                        Wg_p, 2048, bg_p, nullptr, 0,
                                        gates_p, 2048, 2048, 0);
        lstm_attn_kernel<<<32, 256>>>(t, p, mask);
        small_gemm_kernel<<<32, 256>>>(hc_p, 1024, 1024,
                                       W_cat, 512, b_cat, nullptr, 0,
                                       Z_p + (long)t * 32 * 512, 512, 512, 1);
        if (t + 1 < T_) {
            small_gemm_kernel<<<19, 256>>>(hc_p + 512, 1024, 512,
                                           W_red + 300 * 300, 300, nullptr,
                                           Xemb_p + (long)(t + 1) * 32 * 300, 300,
                                           xh_p + (1 - p) * 32 * 812, 812, 300, 0);
        }
    }

    // --- hoisted logits GEMM on tensor cores (bf16 in, fp32 accum) ---
    convz_kernel<<<(1024 * 512 + 255) / 256, 256>>>();
    mma_logits_kernel<<<dim3(NPAD_ / 128, 1024 / 128), 256>>>(Zb_p, Wb_p, b_out, out);

    // --- OOV default (-INF), then pointer scatter-max ---
    oov_fill_kernel<<<(1024 * NOOV_ + 255) / 256, 256>>>(out);
    scatter_kernel<<<1024, 128>>>(ext_src, out);
}